// round 2
// baseline (speedup 1.0000x reference)
#include <cuda_runtime.h>
#include <math_constants.h>

#define N_NODES 50000
#define N_EDGES 1600000
#define IN_C 256
#define HID_C 128
#define OUT_C 16
#define HEADS 8
#define C1 16
#define NEG_SLOPE 0.2f

// ---------------- scratch (device globals; no allocation allowed) ----------------
__device__ __align__(16) float g_h1[N_NODES * HID_C];    // layer-1 transformed features
__device__ __align__(16) float g_h2[N_NODES * HID_C];    // layer-1 output (post bias+relu)
__device__ __align__(16) float g_g2[N_NODES * OUT_C];    // layer-2 transformed features
__device__ float g_asrc1[N_NODES * HEADS];
__device__ float g_adst1[N_NODES * HEADS];
__device__ float g_asrc2[N_NODES];
__device__ float g_adst2[N_NODES];
__device__ int   g_deg[N_NODES];
__device__ int   g_rowptr[N_NODES + 1];
__device__ int   g_cursor[N_NODES];
__device__ int   g_adj[N_EDGES];

// ---------------- GEMM1: h1 = x @ W1  (M x 256) @ (256 x 128) ----------------
#define BM 128
#define BN 128
#define BK 16
__global__ __launch_bounds__(256) void gemm1_kernel(const float* __restrict__ A,
                                                    const float* __restrict__ B, int M) {
    __shared__ float As[BK][BM + 8];   // stride 136 floats = 544B (16B multiple)
    __shared__ float Bs[BK][BN];
    int tid = threadIdx.x;
    int bm = blockIdx.x * BM;
    int tx = tid & 15, ty = tid >> 4;
    float acc[8][8] = {};

    for (int k0 = 0; k0 < IN_C; k0 += BK) {
        // load A tile (BM x BK), store transposed
#pragma unroll
        for (int i = 0; i < 2; i++) {
            int idx = tid + i * 256;
            int ar = idx >> 2;
            int ac = (idx & 3) * 4;
            float4 v = make_float4(0.f, 0.f, 0.f, 0.f);
            int grow = bm + ar;
            if (grow < M) v = *(const float4*)&A[grow * IN_C + k0 + ac];
            As[ac + 0][ar] = v.x;
            As[ac + 1][ar] = v.y;
            As[ac + 2][ar] = v.z;
            As[ac + 3][ar] = v.w;
        }
        // load B tile (BK x BN)
#pragma unroll
        for (int i = 0; i < 2; i++) {
            int idx = tid + i * 256;
            int br = idx >> 5;
            int bc = (idx & 31) * 4;
            *(float4*)&Bs[br][bc] = *(const float4*)&B[(k0 + br) * BN + bc];
        }
        __syncthreads();
#pragma unroll
        for (int k = 0; k < BK; k++) {
            float a[8], b[8];
            *(float4*)&a[0] = *(float4*)&As[k][ty * 8];
            *(float4*)&a[4] = *(float4*)&As[k][ty * 8 + 4];
            *(float4*)&b[0] = *(float4*)&Bs[k][tx * 8];
            *(float4*)&b[4] = *(float4*)&Bs[k][tx * 8 + 4];
#pragma unroll
            for (int i = 0; i < 8; i++)
#pragma unroll
                for (int j = 0; j < 8; j++) acc[i][j] = fmaf(a[i], b[j], acc[i][j]);
        }
        __syncthreads();
    }
#pragma unroll
    for (int i = 0; i < 8; i++) {
        int grow = bm + ty * 8 + i;
        if (grow < M) {
#pragma unroll
            for (int j = 0; j < 8; j += 4) {
                *(float4*)&g_h1[grow * HID_C + tx * 8 + j] =
                    make_float4(acc[i][j], acc[i][j + 1], acc[i][j + 2], acc[i][j + 3]);
            }
        }
    }
}

// ---------------- attention coefficients, layer 1 ----------------
__global__ void attn1_kernel(const float* __restrict__ att_src,
                             const float* __restrict__ att_dst, int N) {
    int idx = blockIdx.x * blockDim.x + threadIdx.x;  // n*8 + h
    if (idx >= N * HEADS) return;
    int h = idx & 7;
    int n = idx >> 3;
    const float* hp = &g_h1[n * HID_C + h * C1];
    float ss = 0.f, sd = 0.f;
#pragma unroll
    for (int c = 0; c < C1; c++) {
        float v = hp[c];
        ss = fmaf(v, att_src[h * C1 + c], ss);
        sd = fmaf(v, att_dst[h * C1 + c], sd);
    }
    g_asrc1[idx] = ss;
    g_adst1[idx] = sd;
}

// ---------------- CSR build ----------------
__global__ void zero_deg_kernel(int N) {
    int i = blockIdx.x * blockDim.x + threadIdx.x;
    if (i < N) g_deg[i] = 0;
}

__global__ void count_kernel(const int* __restrict__ dst, int E) {
    int e = blockIdx.x * blockDim.x + threadIdx.x;
    if (e < E) atomicAdd(&g_deg[dst[e]], 1);
}

__global__ __launch_bounds__(1024) void scan_kernel(int N) {
    __shared__ int sums[1024];
    int t = threadIdx.x;
    int CH = (N + 1023) / 1024;
    int start = t * CH;
    int end = min(start + CH, N);
    int s = 0;
    for (int i = start; i < end; i++) s += g_deg[i];
    sums[t] = s;
    __syncthreads();
    for (int off = 1; off < 1024; off <<= 1) {
        int v = (t >= off) ? sums[t - off] : 0;
        __syncthreads();
        if (t >= off) sums[t] += v;
        __syncthreads();
    }
    int prefix = (t == 0) ? 0 : sums[t - 1];
    for (int i = start; i < end; i++) {
        g_rowptr[i] = prefix;
        g_cursor[i] = prefix;
        prefix += g_deg[i];
    }
    if (t == 1023) g_rowptr[N] = sums[1023];
}

__global__ void scatter_kernel(const int* __restrict__ src, const int* __restrict__ dst, int E) {
    int e = blockIdx.x * blockDim.x + threadIdx.x;
    if (e < E) {
        int d = dst[e];
        int pos = atomicAdd(&g_cursor[d], 1);
        g_adj[pos] = src[e];
    }
}

// ---------------- layer-1 aggregation: warp per node, online softmax ----------------
__global__ __launch_bounds__(256) void agg1_kernel(const float* __restrict__ bias1, int N) {
    int gw = (blockIdx.x * blockDim.x + threadIdx.x) >> 5;
    if (gw >= N) return;
    int lane = threadIdx.x & 31;
    int head = lane >> 2;      // 4 lanes per head
    int c0 = lane * 4;         // this lane's 4 channels in [0,128)

    float adst = g_adst1[gw * HEADS + head];

    // self loop
    float a0 = g_asrc1[gw * HEADS + head] + adst;
    a0 = (a0 > 0.f) ? a0 : NEG_SLOPE * a0;
    float m = a0;
    float s = 1.f;
    float4 acc = *(const float4*)&g_h1[gw * HID_C + c0];

    int beg = g_rowptr[gw];
    int end = g_rowptr[gw + 1];
    for (int e = beg; e < end; e++) {
        int src = g_adj[e];
        float tmp = (lane < HEADS) ? g_asrc1[src * HEADS + lane] : 0.f;
        float asrc = __shfl_sync(0xffffffffu, tmp, head);
        float a = asrc + adst;
        a = (a > 0.f) ? a : NEG_SLOPE * a;
        float nm = fmaxf(m, a);
        float corr = __expf(m - nm);
        float p = __expf(a - nm);
        s = s * corr + p;
        float4 hv = *(const float4*)&g_h1[src * HID_C + c0];
        acc.x = fmaf(p, hv.x, acc.x * corr);
        acc.y = fmaf(p, hv.y, acc.y * corr);
        acc.z = fmaf(p, hv.z, acc.z * corr);
        acc.w = fmaf(p, hv.w, acc.w * corr);
        m = nm;
    }
    float inv = 1.f / s;
    float4 o;
    o.x = fmaxf(fmaf(acc.x, inv, bias1[c0 + 0]), 0.f);
    o.y = fmaxf(fmaf(acc.y, inv, bias1[c0 + 1]), 0.f);
    o.z = fmaxf(fmaf(acc.z, inv, bias1[c0 + 2]), 0.f);
    o.w = fmaxf(fmaf(acc.w, inv, bias1[c0 + 3]), 0.f);
    *(float4*)&g_h2[gw * HID_C + c0] = o;
}

// ---------------- layer 2: g2 = h2 @ W2 (+ attention scores), fused ----------------
__global__ __launch_bounds__(256) void gemm2_kernel(const float* __restrict__ W2,
                                                    const float* __restrict__ att_src,
                                                    const float* __restrict__ att_dst, int N) {
    __shared__ float Ws[HID_C * OUT_C];   // 128x16
    __shared__ float Hs[16][HID_C];       // 16 node rows
    int tid = threadIdx.x;
    int nodeBase = blockIdx.x * 16;
    for (int i = tid; i < HID_C * OUT_C; i += 256) Ws[i] = W2[i];
    int lnode = tid >> 4;
    int seg = tid & 15;
    int gnode = nodeBase + lnode;
    if (gnode < N) {
        *(float4*)&Hs[lnode][seg * 8]     = *(const float4*)&g_h2[gnode * HID_C + seg * 8];
        *(float4*)&Hs[lnode][seg * 8 + 4] = *(const float4*)&g_h2[gnode * HID_C + seg * 8 + 4];
    }
    __syncthreads();
    int j = tid & 15;
    float acc = 0.f;
#pragma unroll 8
    for (int c = 0; c < HID_C; c++) acc = fmaf(Hs[lnode][c], Ws[c * OUT_C + j], acc);
    float vs = acc * att_src[j];
    float vd = acc * att_dst[j];
#pragma unroll
    for (int off = 8; off; off >>= 1) {
        vs += __shfl_down_sync(0xffffffffu, vs, off, 16);
        vd += __shfl_down_sync(0xffffffffu, vd, off, 16);
    }
    if (gnode < N) {
        g_g2[gnode * OUT_C + j] = acc;
        if (j == 0) {
            g_asrc2[gnode] = vs;
            g_adst2[gnode] = vd;
        }
    }
}

// ---------------- layer-2 aggregation: warp per node, 2 edges/iter ----------------
__global__ __launch_bounds__(256) void agg2_kernel(const float* __restrict__ bias2,
                                                   float* __restrict__ out, int N) {
    int gw = (blockIdx.x * blockDim.x + threadIdx.x) >> 5;
    if (gw >= N) return;
    int lane = threadIdx.x & 31;
    int half = lane >> 4;
    int c = lane & 15;

    float adst = g_adst2[gw];
    int beg = g_rowptr[gw];
    int end = g_rowptr[gw + 1];
    int cnt = end - beg;
    int nlow = cnt >> 1;

    float m, s, acc;
    int ebeg, eend;
    if (half == 0) {
        ebeg = beg;
        eend = beg + nlow;
        float a0 = g_asrc2[gw] + adst;
        a0 = (a0 > 0.f) ? a0 : NEG_SLOPE * a0;
        m = a0;
        s = 1.f;
        acc = g_g2[gw * OUT_C + c];
    } else {
        ebeg = beg + nlow;
        eend = end;
        m = -CUDART_INF_F;
        s = 0.f;
        acc = 0.f;
    }
    for (int e = ebeg; e < eend; e++) {
        int src = g_adj[e];
        float asrc = g_asrc2[src];
        float a = asrc + adst;
        a = (a > 0.f) ? a : NEG_SLOPE * a;
        float nm = fmaxf(m, a);
        float corr = __expf(m - nm);
        float p = __expf(a - nm);
        s = s * corr + p;
        acc = fmaf(p, g_g2[src * OUT_C + c], acc * corr);
        m = nm;
    }
    // merge the two halves
    float om = __shfl_xor_sync(0xffffffffu, m, 16);
    float os = __shfl_xor_sync(0xffffffffu, s, 16);
    float oa = __shfl_xor_sync(0xffffffffu, acc, 16);
    float M2 = fmaxf(m, om);
    float ca = __expf(m - M2);
    float cb = __expf(om - M2);
    float S = s * ca + os * cb;
    float A = acc * ca + oa * cb;
    if (half == 0) out[gw * OUT_C + c] = A / S + bias2[c];
}

// ---------------- launch ----------------
extern "C" void kernel_launch(void* const* d_in, const int* in_sizes, int n_in,
                              void* d_out, int out_size) {
    const float* x        = (const float*)d_in[0];
    const int*   eidx     = (const int*)d_in[1];
    const float* W1       = (const float*)d_in[2];
    const float* att_src1 = (const float*)d_in[3];
    const float* att_dst1 = (const float*)d_in[4];
    const float* bias1    = (const float*)d_in[5];
    const float* W2       = (const float*)d_in[6];
    const float* att_src2 = (const float*)d_in[7];
    const float* att_dst2 = (const float*)d_in[8];
    const float* bias2    = (const float*)d_in[9];
    float* out = (float*)d_out;

    int N = in_sizes[0] / IN_C;
    int E = in_sizes[1] / 2;
    const int* srcArr = eidx;
    const int* dstArr = eidx + E;

    // GEMM1
    gemm1_kernel<<<(N + BM - 1) / BM, 256>>>(x, W1, N);
    // attention coefficients layer 1
    attn1_kernel<<<(N * HEADS + 255) / 256, 256>>>(att_src1, att_dst1, N);
    // CSR build
    zero_deg_kernel<<<(N + 255) / 256, 256>>>(N);
    count_kernel<<<(E + 255) / 256, 256>>>(dstArr, E);
    scan_kernel<<<1, 1024>>>(N);
    scatter_kernel<<<(E + 255) / 256, 256>>>(srcArr, dstArr, E);
    // layer-1 aggregation
    agg1_kernel<<<(N * 32 + 255) / 256, 256>>>(bias1, N);
    // layer 2 transform + attention scores
    gemm2_kernel<<<(N + 15) / 16, 256>>>(W2, att_src2, att_dst2, N);
    // layer-2 aggregation -> output
    agg2_kernel<<<(N * 32 + 255) / 256, 256>>>(bias2, out, N);
}

// round 3
// speedup vs baseline: 1.0245x; 1.0245x over previous
#include <cuda_runtime.h>
#include <math_constants.h>

#define N_NODES 50000
#define N_EDGES 1600000
#define IN_C 256
#define HID_C 128
#define OUT_C 16
#define HEADS 8
#define C1 16
#define NEG_SLOPE 0.2f

// ---------------- scratch (device globals; no allocation allowed) ----------------
__device__ __align__(16) float g_h1[N_NODES * HID_C];    // layer-1 transformed features
__device__ __align__(16) float g_h2[N_NODES * HID_C];    // layer-1 output (post bias+relu)
__device__ __align__(16) float g_g2[N_NODES * OUT_C];    // layer-2 transformed features
__device__ float g_asrc1[N_NODES * HEADS];
__device__ float g_adst1[N_NODES * HEADS];
__device__ float g_amax1[N_NODES * HEADS];
__device__ float g_asrc2[N_NODES];
__device__ float g_adst2[N_NODES];
__device__ float g_amax2[N_NODES];
__device__ int   g_deg[N_NODES];
__device__ int   g_rowptr[N_NODES + 1];
__device__ int   g_cursor[N_NODES];
__device__ int   g_adj[N_EDGES];

__device__ __forceinline__ float leaky(float a) {
    return (a > 0.f) ? a : NEG_SLOPE * a;
}

// ---------------- GEMM1: h1 = x @ W1  (M x 256) @ (256 x 128), packed f32x2 ----------------
#define BM 128
#define BN 128
#define BK 16
__global__ __launch_bounds__(256) void gemm1_kernel(const float* __restrict__ A,
                                                    const float* __restrict__ B, int M) {
    __shared__ __align__(16) float As[BK][BM + 8];   // stride 136 floats
    __shared__ __align__(16) float Bs[BK][BN];
    int tid = threadIdx.x;
    int bm = blockIdx.x * BM;
    int tx = tid & 15, ty = tid >> 4;
    unsigned long long acc2[8][4];   // 8 rows x 4 channel-pairs (f32x2)
#pragma unroll
    for (int i = 0; i < 8; i++)
#pragma unroll
        for (int j = 0; j < 4; j++) acc2[i][j] = 0ULL;

    for (int k0 = 0; k0 < IN_C; k0 += BK) {
        // load A tile (BM x BK), store transposed
#pragma unroll
        for (int i = 0; i < 2; i++) {
            int idx = tid + i * 256;
            int ar = idx >> 2;
            int ac = (idx & 3) * 4;
            float4 v = make_float4(0.f, 0.f, 0.f, 0.f);
            int grow = bm + ar;
            if (grow < M) v = *(const float4*)&A[grow * IN_C + k0 + ac];
            As[ac + 0][ar] = v.x;
            As[ac + 1][ar] = v.y;
            As[ac + 2][ar] = v.z;
            As[ac + 3][ar] = v.w;
        }
        // load B tile (BK x BN)
#pragma unroll
        for (int i = 0; i < 2; i++) {
            int idx = tid + i * 256;
            int br = idx >> 5;
            int bc = (idx & 31) * 4;
            *(float4*)&Bs[br][bc] = *(const float4*)&B[(k0 + br) * BN + bc];
        }
        __syncthreads();
#pragma unroll
        for (int k = 0; k < BK; k++) {
            float a[8];
            *(float4*)&a[0] = *(float4*)&As[k][ty * 8];
            *(float4*)&a[4] = *(float4*)&As[k][ty * 8 + 4];
            unsigned long long b2[4];
            {
                const ulonglong2* bp = (const ulonglong2*)&Bs[k][tx * 8];
                ulonglong2 bv0 = bp[0];
                ulonglong2 bv1 = bp[1];
                b2[0] = bv0.x; b2[1] = bv0.y; b2[2] = bv1.x; b2[3] = bv1.y;
            }
            unsigned long long ad[8];
#pragma unroll
            for (int i = 0; i < 8; i++)
                asm("mov.b64 %0, {%1, %1};" : "=l"(ad[i]) : "f"(a[i]));
#pragma unroll
            for (int i = 0; i < 8; i++)
#pragma unroll
                for (int j = 0; j < 4; j++)
                    asm("fma.rn.f32x2 %0, %1, %2, %3;"
                        : "=l"(acc2[i][j]) : "l"(ad[i]), "l"(b2[j]), "l"(acc2[i][j]));
        }
        __syncthreads();
    }
#pragma unroll
    for (int i = 0; i < 8; i++) {
        int grow = bm + ty * 8 + i;
        if (grow < M) {
            ulonglong2 s0, s1;
            s0.x = acc2[i][0]; s0.y = acc2[i][1];
            s1.x = acc2[i][2]; s1.y = acc2[i][3];
            *(ulonglong2*)&g_h1[grow * HID_C + tx * 8]     = s0;
            *(ulonglong2*)&g_h1[grow * HID_C + tx * 8 + 4] = s1;
        }
    }
}

// ---------------- attention coefficients, layer 1 ----------------
__global__ void attn1_kernel(const float* __restrict__ att_src,
                             const float* __restrict__ att_dst, int N) {
    int idx = blockIdx.x * blockDim.x + threadIdx.x;  // n*8 + h
    if (idx >= N * HEADS) return;
    int h = idx & 7;
    int n = idx >> 3;
    const float* hp = &g_h1[n * HID_C + h * C1];
    float ss = 0.f, sd = 0.f;
#pragma unroll
    for (int c = 0; c < C1; c++) {
        float v = hp[c];
        ss = fmaf(v, att_src[h * C1 + c], ss);
        sd = fmaf(v, att_dst[h * C1 + c], sd);
    }
    g_asrc1[idx] = ss;
    g_adst1[idx] = sd;
}

// ---------------- CSR build ----------------
__global__ void zero_deg_kernel(int N) {
    int i = blockIdx.x * blockDim.x + threadIdx.x;
    if (i < N) g_deg[i] = 0;
}

__global__ void count_kernel(const int* __restrict__ dst, int E) {
    int e = blockIdx.x * blockDim.x + threadIdx.x;
    if (e < E) atomicAdd(&g_deg[dst[e]], 1);
}

__global__ __launch_bounds__(1024) void scan_kernel(int N) {
    __shared__ int sums[1024];
    int t = threadIdx.x;
    int CH = (N + 1023) / 1024;
    int start = t * CH;
    int end = min(start + CH, N);
    int s = 0;
    for (int i = start; i < end; i++) s += g_deg[i];
    sums[t] = s;
    __syncthreads();
    for (int off = 1; off < 1024; off <<= 1) {
        int v = (t >= off) ? sums[t - off] : 0;
        __syncthreads();
        if (t >= off) sums[t] += v;
        __syncthreads();
    }
    int prefix = (t == 0) ? 0 : sums[t - 1];
    for (int i = start; i < end; i++) {
        g_rowptr[i] = prefix;
        g_cursor[i] = prefix;
        prefix += g_deg[i];
    }
    if (t == 1023) g_rowptr[N] = sums[1023];
}

__global__ void scatter_kernel(const int* __restrict__ src, const int* __restrict__ dst, int E) {
    int e = blockIdx.x * blockDim.x + threadIdx.x;
    if (e < E) {
        int d = dst[e];
        int pos = atomicAdd(&g_cursor[d], 1);
        g_adj[pos] = src[e];
    }
}

// ---------------- layer-1 max pass: amax1[n,h] = leaky(max(src scores) + adst) ----------------
__global__ __launch_bounds__(256) void maxpass1_kernel(int N) {
    int gw = (blockIdx.x * blockDim.x + threadIdx.x) >> 5;
    if (gw >= N) return;
    int lane = threadIdx.x & 31;
    int h = lane & 7;
    int g = lane >> 3;  // 4 edge groups
    int beg = g_rowptr[gw];
    int end = g_rowptr[gw + 1];
    float mx = -CUDART_INF_F;
    for (int e = beg + g; e < end; e += 4) {
        int src = g_adj[e];
        mx = fmaxf(mx, g_asrc1[src * HEADS + h]);
    }
    mx = fmaxf(mx, __shfl_xor_sync(0xffffffffu, mx, 8));
    mx = fmaxf(mx, __shfl_xor_sync(0xffffffffu, mx, 16));
    mx = fmaxf(mx, g_asrc1[gw * HEADS + h]);  // self loop
    float a = leaky(mx + g_adst1[gw * HEADS + h]);
    if (lane < 8) g_amax1[gw * HEADS + h] = a;
}

// ---------------- layer-1 aggregation: warp per node, single-exp weighted sum ----------------
__global__ __launch_bounds__(256) void agg1_kernel(const float* __restrict__ bias1, int N) {
    int gw = (blockIdx.x * blockDim.x + threadIdx.x) >> 5;
    if (gw >= N) return;
    int lane = threadIdx.x & 31;
    int head = lane >> 2;      // 4 lanes per head
    int c0 = lane * 4;         // this lane's 4 channels in [0,128)

    float adst = g_adst1[gw * HEADS + head];
    float amax = g_amax1[gw * HEADS + head];

    // self loop
    float p0 = __expf(leaky(g_asrc1[gw * HEADS + head] + adst) - amax);
    float s = p0;
    float4 hs = *(const float4*)&g_h1[gw * HID_C + c0];
    float4 acc = make_float4(p0 * hs.x, p0 * hs.y, p0 * hs.z, p0 * hs.w);

    int beg = g_rowptr[gw];
    int end = g_rowptr[gw + 1];
#pragma unroll 2
    for (int e = beg; e < end; e++) {
        int src = g_adj[e];
        float t = g_asrc1[src * HEADS + head];
        float p = __expf(leaky(t + adst) - amax);
        float4 hv = *(const float4*)&g_h1[src * HID_C + c0];
        s += p;
        acc.x = fmaf(p, hv.x, acc.x);
        acc.y = fmaf(p, hv.y, acc.y);
        acc.z = fmaf(p, hv.z, acc.z);
        acc.w = fmaf(p, hv.w, acc.w);
    }
    float inv = 1.f / s;
    float4 o;
    o.x = fmaxf(fmaf(acc.x, inv, bias1[c0 + 0]), 0.f);
    o.y = fmaxf(fmaf(acc.y, inv, bias1[c0 + 1]), 0.f);
    o.z = fmaxf(fmaf(acc.z, inv, bias1[c0 + 2]), 0.f);
    o.w = fmaxf(fmaf(acc.w, inv, bias1[c0 + 3]), 0.f);
    *(float4*)&g_h2[gw * HID_C + c0] = o;
}

// ---------------- layer 2: g2 = h2 @ W2 (+ attention scores), fused ----------------
__global__ __launch_bounds__(256) void gemm2_kernel(const float* __restrict__ W2,
                                                    const float* __restrict__ att_src,
                                                    const float* __restrict__ att_dst, int N) {
    __shared__ float Ws[HID_C * OUT_C];   // 128x16
    __shared__ float Hs[16][HID_C];       // 16 node rows
    int tid = threadIdx.x;
    int nodeBase = blockIdx.x * 16;
    for (int i = tid; i < HID_C * OUT_C; i += 256) Ws[i] = W2[i];
    int lnode = tid >> 4;
    int seg = tid & 15;
    int gnode = nodeBase + lnode;
    if (gnode < N) {
        *(float4*)&Hs[lnode][seg * 8]     = *(const float4*)&g_h2[gnode * HID_C + seg * 8];
        *(float4*)&Hs[lnode][seg * 8 + 4] = *(const float4*)&g_h2[gnode * HID_C + seg * 8 + 4];
    }
    __syncthreads();
    int j = tid & 15;
    float acc = 0.f;
#pragma unroll 8
    for (int c = 0; c < HID_C; c++) acc = fmaf(Hs[lnode][c], Ws[c * OUT_C + j], acc);
    float vs = acc * att_src[j];
    float vd = acc * att_dst[j];
#pragma unroll
    for (int off = 8; off; off >>= 1) {
        vs += __shfl_down_sync(0xffffffffu, vs, off, 16);
        vd += __shfl_down_sync(0xffffffffu, vd, off, 16);
    }
    if (gnode < N) {
        g_g2[gnode * OUT_C + j] = acc;
        if (j == 0) {
            g_asrc2[gnode] = vs;
            g_adst2[gnode] = vd;
        }
    }
}

// ---------------- layer-2 max pass ----------------
__global__ __launch_bounds__(256) void maxpass2_kernel(int N) {
    int gw = (blockIdx.x * blockDim.x + threadIdx.x) >> 5;
    if (gw >= N) return;
    int lane = threadIdx.x & 31;
    int beg = g_rowptr[gw];
    int end = g_rowptr[gw + 1];
    float mx = -CUDART_INF_F;
    for (int e = beg + lane; e < end; e += 32) {
        mx = fmaxf(mx, g_asrc2[g_adj[e]]);
    }
#pragma unroll
    for (int off = 16; off; off >>= 1)
        mx = fmaxf(mx, __shfl_xor_sync(0xffffffffu, mx, off));
    mx = fmaxf(mx, g_asrc2[gw]);  // self loop
    float a = leaky(mx + g_adst2[gw]);
    if (lane == 0) g_amax2[gw] = a;
}

// ---------------- layer-2 aggregation: warp per node, 2 edges/iter ----------------
__global__ __launch_bounds__(256) void agg2_kernel(const float* __restrict__ bias2,
                                                   float* __restrict__ out, int N) {
    int gw = (blockIdx.x * blockDim.x + threadIdx.x) >> 5;
    if (gw >= N) return;
    int lane = threadIdx.x & 31;
    int half = lane >> 4;
    int c = lane & 15;

    float adst = g_adst2[gw];
    float amax = g_amax2[gw];
    int beg = g_rowptr[gw];
    int end = g_rowptr[gw + 1];

    float s = 0.f, acc = 0.f;
    if (half == 0) {  // self loop in half 0
        float p0 = __expf(leaky(g_asrc2[gw] + adst) - amax);
        s = p0;
        acc = p0 * g_g2[gw * OUT_C + c];
    }
    for (int e = beg + half; e < end; e += 2) {
        int src = g_adj[e];
        float p = __expf(leaky(g_asrc2[src] + adst) - amax);
        s += p;
        acc = fmaf(p, g_g2[src * OUT_C + c], acc);
    }
    // merge the two halves
    s += __shfl_xor_sync(0xffffffffu, s, 16);
    acc += __shfl_xor_sync(0xffffffffu, acc, 16);
    if (half == 0) out[gw * OUT_C + c] = acc / s + bias2[c];
}

// ---------------- launch ----------------
extern "C" void kernel_launch(void* const* d_in, const int* in_sizes, int n_in,
                              void* d_out, int out_size) {
    const float* x        = (const float*)d_in[0];
    const int*   eidx     = (const int*)d_in[1];
    const float* W1       = (const float*)d_in[2];
    const float* att_src1 = (const float*)d_in[3];
    const float* att_dst1 = (const float*)d_in[4];
    const float* bias1    = (const float*)d_in[5];
    const float* W2       = (const float*)d_in[6];
    const float* att_src2 = (const float*)d_in[7];
    const float* att_dst2 = (const float*)d_in[8];
    const float* bias2    = (const float*)d_in[9];
    float* out = (float*)d_out;

    int N = in_sizes[0] / IN_C;
    int E = in_sizes[1] / 2;
    const int* srcArr = eidx;
    const int* dstArr = eidx + E;

    // GEMM1
    gemm1_kernel<<<(N + BM - 1) / BM, 256>>>(x, W1, N);
    // attention coefficients layer 1
    attn1_kernel<<<(N * HEADS + 255) / 256, 256>>>(att_src1, att_dst1, N);
    // CSR build
    zero_deg_kernel<<<(N + 255) / 256, 256>>>(N);
    count_kernel<<<(E + 255) / 256, 256>>>(dstArr, E);
    scan_kernel<<<1, 1024>>>(N);
    scatter_kernel<<<(E + 255) / 256, 256>>>(srcArr, dstArr, E);
    // layer-1 softmax max precompute + aggregation
    maxpass1_kernel<<<(N * 32 + 255) / 256, 256>>>(N);
    agg1_kernel<<<(N * 32 + 255) / 256, 256>>>(bias1, N);
    // layer 2 transform + attention scores
    gemm2_kernel<<<(N + 15) / 16, 256>>>(W2, att_src2, att_dst2, N);
    // layer-2 softmax max precompute + aggregation -> output
    maxpass2_kernel<<<(N * 32 + 255) / 256, 256>>>(N);
    agg2_kernel<<<(N * 32 + 255) / 256, 256>>>(bias2, out, N);
}